// round 13
// baseline (speedup 1.0000x reference)
#include <cuda_runtime.h>
#include <cuda_bf16.h>
#include <math.h>

// GRNNTransformGated via mma.sync.m16n8k16 bf16 (3-pass split ~ fp32 precision).
// B operands pre-packed in gmem in mma-fragment order (one-time prep_pack):
// warps load B fragments via coalesced LDG.128 -> no B smem staging, 3 syncs/block.
// ROWS=64, NT=512 (16 warps, 2m x 8n, MT=2).

#define NT 512
#define ROWS 64
#define MT 2
#define SAB 528   // A buf row stride bytes; (528/4)%32=4 -> ldmatrix conflict-free
#define SRB 400   // rx buf row stride bytes; (400/4)%32=4

__device__ float g_upA[262144 * 64];
__device__ float g_upB[131072 * 64];

// fragment-packed weights: idx = ((gn*KG + kg)*2 + bsel)*32 + lane, uint4 = 4 k-steps
__device__ uint4 g_PrH[4608], g_PrL[4608];   // W_r: N=192 (gn 24), K=192 (KG 3)
__device__ uint4 g_PhH[1536], g_PhL[1536];   // W_h: N=64  (gn 8),  K=192 (KG 3)
__device__ uint4 g_PzH[8192], g_PzL[8192];   // W_z: N=256 (gn 32), K=256 (KG 4)

__device__ __forceinline__ void split_pack(float a, float b, unsigned& hi, unsigned& lo) {
    __nv_bfloat16 ha = __float2bfloat16(a), hb = __float2bfloat16(b);
    __nv_bfloat16 la = __float2bfloat16(a - __bfloat162float(ha));
    __nv_bfloat16 lb = __float2bfloat16(b - __bfloat162float(hb));
    hi = (unsigned)__bfloat16_as_ushort(ha) | ((unsigned)__bfloat16_as_ushort(hb) << 16);
    lo = (unsigned)__bfloat16_as_ushort(la) | ((unsigned)__bfloat16_as_ushort(lb) << 16);
}
__device__ __forceinline__ float rd_split(const char* hi, const char* lo, int row, int col, int strideB) {
    return __bfloat162float(*(const __nv_bfloat16*)(hi + row * strideB + col * 2)) +
           __bfloat162float(*(const __nv_bfloat16*)(lo + row * strideB + col * 2));
}
__device__ __forceinline__ unsigned smem_u32(const void* p) {
    unsigned a;
    asm("{ .reg .u64 t; cvta.to.shared.u64 t, %1; cvt.u32.u64 %0, t; }" : "=r"(a) : "l"(p));
    return a;
}
__device__ __forceinline__ void mma16816(float* c, const unsigned* a, const unsigned* b) {
    asm volatile("mma.sync.aligned.m16n8k16.row.col.f32.bf16.bf16.f32 "
                 "{%0,%1,%2,%3}, {%4,%5,%6,%7}, {%8,%9}, {%0,%1,%2,%3};"
                 : "+f"(c[0]), "+f"(c[1]), "+f"(c[2]), "+f"(c[3])
                 : "r"(a[0]), "r"(a[1]), "r"(a[2]), "r"(a[3]), "r"(b[0]), "r"(b[1]));
}
#define LDSM_X4(d, addr) \
    asm volatile("ldmatrix.sync.aligned.m8n8.x4.shared.b16 {%0,%1,%2,%3}, [%4];" \
                 : "=r"((d)[0]), "=r"((d)[1]), "=r"((d)[2]), "=r"((d)[3]) : "r"(addr))
#define UNPACK4(q, v) do { (q)[0] = (v).x; (q)[1] = (v).y; (q)[2] = (v).z; (q)[3] = (v).w; } while (0)

// ---------------- one-time: pack W[N][K] fp32 into fragment-order bf16 hi/lo ----------------
__global__ void prep_pack(const float* __restrict__ W, int N, int K,
                          uint4* __restrict__ Ph, uint4* __restrict__ Pl) {
    int id = blockIdx.x * blockDim.x + threadIdx.x;
    int KG = K >> 6;
    int total = (N >> 3) * KG * 2 * 32;
    if (id >= total) return;
    int lane = id & 31, bsel = (id >> 5) & 1, rest = id >> 6;
    int kg = rest % KG, gn = rest / KG;
    int n = gn * 8 + (lane >> 2);
    unsigned hw[4], lw[4];
#pragma unroll
    for (int j = 0; j < 4; j++) {
        int k = kg * 64 + j * 16 + bsel * 8 + (lane & 3) * 2;
        split_pack(W[(size_t)n * K + k], W[(size_t)n * K + k + 1], hw[j], lw[j]);
    }
    Ph[id] = make_uint4(hw[0], hw[1], hw[2], hw[3]);
    Pl[id] = make_uint4(lw[0], lw[1], lw[2], lw[3]);
}

// ---------------- top level (j=12) ----------------
__global__ void grnn_top_kernel(const float* __restrict__ contents,
                                const float* __restrict__ W_u,
                                const float* __restrict__ b_u,
                                float* __restrict__ up, int n) {
    int idx = blockIdx.x * blockDim.x + threadIdx.x;
    if (idx >= n * 64) return;
    int i = idx >> 6, h = idx & 63;
    const float* c = contents + (size_t)i * 7;
    const float* w = W_u + h * 7;
    float acc = b_u[h];
#pragma unroll
    for (int f = 0; f < 7; f++) acc = fmaf(__ldg(c + f), __ldg(w + f), acc);
    up[idx] = fmaxf(acc, 0.f);
}

// ---------------- fused level kernel: 64 rows / block, 3 syncs ----------------
__global__ __launch_bounds__(NT, 1) void grnn_level_kernel(
    const float* __restrict__ contents,
    const float* __restrict__ up_prev,
    float* __restrict__ up_out,
    const float* __restrict__ W_u, const float* __restrict__ b_u,
    const uint4* __restrict__ PrH, const uint4* __restrict__ PrL,
    const float* __restrict__ b_r,
    const uint4* __restrict__ PhH, const uint4* __restrict__ PhL,
    const float* __restrict__ b_h,
    const uint4* __restrict__ PzH, const uint4* __restrict__ PzL,
    const float* __restrict__ b_z)
{
    constexpr int OF_ALO = ROWS * SAB;                 // 33792
    constexpr int OF_RHI = OF_ALO + ROWS * SAB;        // 67584
    constexpr int OF_RLO = OF_RHI + ROWS * SRB;        // 93184
    constexpr int OF_CS  = OF_RLO + ROWS * SRB;        // 118784
    constexpr int OF_WU  = OF_CS + ROWS * 8 * 4;
    constexpr int OF_BUS = OF_WU + 64 * 8 * 4;

    extern __shared__ char sm[];
    char* AHI = sm;            char* ALO = sm + OF_ALO;
    char* RHI = sm + OF_RHI;   char* RLO = sm + OF_RLO;
    float* cs  = (float*)(sm + OF_CS);
    float* wu  = (float*)(sm + OF_WU);
    float* bus = (float*)(sm + OF_BUS);

    const unsigned smb = smem_u32(sm);
    const unsigned uAHI = smb, uALO = smb + OF_ALO;
    const unsigned uRHI = smb + OF_RHI, uRLO = smb + OF_RLO;

    const int t = threadIdx.x, lane = t & 31, w = t >> 5;
    const int wm = w >> 3, wn = w & 7, g = lane >> 2, tg = lane & 3;
    const int l16 = lane & 15;
    const unsigned aSel = ((lane >> 4) & 1) * 16;
    const int r0 = blockIdx.x * ROWS;

    // ---- phase 0a: stage contents/W_u/b_u; load+split h_L,h_R -> cols 64..191 ----
    for (int idx = t; idx < ROWS * 7; idx += NT) {
        int i = idx / 7, f = idx % 7;
        cs[i * 8 + f] = contents[(size_t)(r0 + i) * 7 + f];
    }
    for (int idx = t; idx < 64 * 7; idx += NT) wu[(idx / 7) * 8 + (idx % 7)] = W_u[idx];
    if (t < 64) bus[t] = b_u[t];
    for (int idx = t; idx < ROWS * 32; idx += NT) {
        int i = idx >> 5, q = idx & 31, side = q >> 4, qq = q & 15;
        float4 v = *(const float4*)(up_prev + ((size_t)2 * (r0 + i) + side) * 64 + qq * 4);
        unsigned h0, l0, h1, l1;
        split_pack(v.x, v.y, h0, l0); split_pack(v.z, v.w, h1, l1);
        int col = 64 + side * 64 + qq * 4;
        *(uint2*)(AHI + i * SAB + col * 2) = make_uint2(h0, h1);
        *(uint2*)(ALO + i * SAB + col * 2) = make_uint2(l0, l1);
    }
    __syncthreads();                                   // cs/wu/bus visible
    // ---- phase 0b: u = relu(c @ W_u^T + b_u) -> cols 192..255 ----
    for (int idx = t; idx < ROWS * 32; idx += NT) {
        int i = idx >> 5, cp = idx & 31;
        float a0 = bus[2 * cp], a1 = bus[2 * cp + 1];
#pragma unroll
        for (int f = 0; f < 7; f++) {
            float cv = cs[i * 8 + f];
            a0 = fmaf(cv, wu[(2 * cp) * 8 + f], a0);
            a1 = fmaf(cv, wu[(2 * cp + 1) * 8 + f], a1);
        }
        a0 = fmaxf(a0, 0.f); a1 = fmaxf(a1, 0.f);
        unsigned hi, lo; split_pack(a0, a1, hi, lo);
        *(unsigned*)(AHI + i * SAB + (192 + 2 * cp) * 2) = hi;
        *(unsigned*)(ALO + i * SAB + (192 + 2 * cp) * 2) = lo;
    }
    __syncthreads();                                   // hhu complete

    // ---- GEMM1: rx = sigmoid(hhu @ W_r^T + b_r) * hhu; B frags via LDG.128 ----
    float acc1[3][MT][4] = {};
#pragma unroll
    for (int kg = 0; kg < 3; kg++) {
        unsigned q0h[3][4], q1h[3][4], q0l[3][4], q1l[3][4];
#pragma unroll
        for (int c = 0; c < 3; c++) {
            int base = ((c * 8 + wn) * 3 + kg) * 64 + lane;
            uint4 v;
            v = __ldg(PrH + base);      UNPACK4(q0h[c], v);
            v = __ldg(PrH + base + 32); UNPACK4(q1h[c], v);
            v = __ldg(PrL + base);      UNPACK4(q0l[c], v);
            v = __ldg(PrL + base + 32); UNPACK4(q1l[c], v);
        }
#pragma unroll
        for (int j = 0; j < 4; j++) {
            int kk = kg * 4 + j;
            unsigned ah[MT][4], al[MT][4];
#pragma unroll
            for (int mt = 0; mt < MT; mt++) {
                unsigned off = (unsigned)(((wm * MT + mt) * 16 + l16) * SAB
                                          + (64 + kk * 16) * 2) + aSel;
                LDSM_X4(ah[mt], uAHI + off);
                LDSM_X4(al[mt], uALO + off);
            }
            unsigned bh[3][2], bl[3][2];
#pragma unroll
            for (int c = 0; c < 3; c++) {
                bh[c][0] = q0h[c][j]; bh[c][1] = q1h[c][j];
                bl[c][0] = q0l[c][j]; bl[c][1] = q1l[c][j];
            }
#pragma unroll
            for (int c = 0; c < 3; c++)
#pragma unroll
                for (int mt = 0; mt < MT; mt++) mma16816(acc1[c][mt], ah[mt], bh[c]);
#pragma unroll
            for (int c = 0; c < 3; c++)
#pragma unroll
                for (int mt = 0; mt < MT; mt++) mma16816(acc1[c][mt], ah[mt], bl[c]);
#pragma unroll
            for (int c = 0; c < 3; c++)
#pragma unroll
                for (int mt = 0; mt < MT; mt++) mma16816(acc1[c][mt], al[mt], bh[c]);
        }
    }
    // epilogue 1: rx -> RHI/RLO
#pragma unroll
    for (int c = 0; c < 3; c++)
#pragma unroll
        for (int mt = 0; mt < MT; mt++)
#pragma unroll
            for (int rs = 0; rs < 2; rs++) {
                int row = (wm * MT + mt) * 16 + g + rs * 8;
                int o0 = c * 64 + wn * 8 + 2 * tg;
                float z0 = acc1[c][mt][rs * 2 + 0] + __ldg(b_r + o0);
                float z1 = acc1[c][mt][rs * 2 + 1] + __ldg(b_r + o0 + 1);
                float s0 = 1.f / (1.f + __expf(-z0));
                float s1 = 1.f / (1.f + __expf(-z1));
                float x0 = s0 * rd_split(AHI, ALO, row, 64 + o0, SAB);
                float x1 = s1 * rd_split(AHI, ALO, row, 64 + o0 + 1, SAB);
                unsigned hi, lo; split_pack(x0, x1, hi, lo);
                *(unsigned*)(RHI + row * SRB + o0 * 2) = hi;
                *(unsigned*)(RLO + row * SRB + o0 * 2) = lo;
            }
    __syncthreads();                                   // rx visible across warps

    // ---- GEMM2: h_H = relu(rx @ W_h^T + b_h) -> AHI cols 0..63 ----
    {
        float acc[MT][4] = {};
#pragma unroll
        for (int kg = 0; kg < 3; kg++) {
            unsigned q0h[4], q1h[4], q0l[4], q1l[4];
            int base = (wn * 3 + kg) * 64 + lane;
            uint4 v;
            v = __ldg(PhH + base);      UNPACK4(q0h, v);
            v = __ldg(PhH + base + 32); UNPACK4(q1h, v);
            v = __ldg(PhL + base);      UNPACK4(q0l, v);
            v = __ldg(PhL + base + 32); UNPACK4(q1l, v);
#pragma unroll
            for (int j = 0; j < 4; j++) {
                int kk = kg * 4 + j;
                unsigned ah[MT][4], al[MT][4];
#pragma unroll
                for (int mt = 0; mt < MT; mt++) {
                    unsigned off = (unsigned)(((wm * MT + mt) * 16 + l16) * SRB + kk * 32) + aSel;
                    LDSM_X4(ah[mt], uRHI + off);
                    LDSM_X4(al[mt], uRLO + off);
                }
                unsigned bh[2] = { q0h[j], q1h[j] }, bl[2] = { q0l[j], q1l[j] };
#pragma unroll
                for (int mt = 0; mt < MT; mt++) mma16816(acc[mt], ah[mt], bh);
#pragma unroll
                for (int mt = 0; mt < MT; mt++) mma16816(acc[mt], ah[mt], bl);
#pragma unroll
                for (int mt = 0; mt < MT; mt++) mma16816(acc[mt], al[mt], bh);
            }
        }
        // epilogue 2: hH -> AHI/ALO cols 0..63
#pragma unroll
        for (int mt = 0; mt < MT; mt++)
#pragma unroll
            for (int rs = 0; rs < 2; rs++) {
                int row = (wm * MT + mt) * 16 + g + rs * 8;
                int h0 = wn * 8 + 2 * tg;
                float v0 = fmaxf(acc[mt][rs * 2 + 0] + __ldg(b_h + h0), 0.f);
                float v1 = fmaxf(acc[mt][rs * 2 + 1] + __ldg(b_h + h0 + 1), 0.f);
                unsigned hi, lo; split_pack(v0, v1, hi, lo);
                *(unsigned*)(AHI + row * SAB + h0 * 2) = hi;
                *(unsigned*)(ALO + row * SAB + h0 * 2) = lo;
            }
    }
    __syncthreads();                                   // hH visible across warps

    // ---- GEMM3: z = [h_H | hhu] @ W_z^T + b_z; 2 c-pairs to bound registers ----
    float acc3[4][MT][4] = {};
#pragma unroll
    for (int pair = 0; pair < 2; pair++) {
#pragma unroll
        for (int kg = 0; kg < 4; kg++) {
            unsigned q0h[2][4], q1h[2][4], q0l[2][4], q1l[2][4];
#pragma unroll
            for (int cc = 0; cc < 2; cc++) {
                int base = (((pair * 2 + cc) * 8 + wn) * 4 + kg) * 64 + lane;
                uint4 v;
                v = __ldg(PzH + base);      UNPACK4(q0h[cc], v);
                v = __ldg(PzH + base + 32); UNPACK4(q1h[cc], v);
                v = __ldg(PzL + base);      UNPACK4(q0l[cc], v);
                v = __ldg(PzL + base + 32); UNPACK4(q1l[cc], v);
            }
#pragma unroll
            for (int j = 0; j < 4; j++) {
                int kk = kg * 4 + j;
                unsigned ah[MT][4], al[MT][4];
#pragma unroll
                for (int mt = 0; mt < MT; mt++) {
                    unsigned off = (unsigned)(((wm * MT + mt) * 16 + l16) * SAB
                                              + kk * 32) + aSel;
                    LDSM_X4(ah[mt], uAHI + off);
                    LDSM_X4(al[mt], uALO + off);
                }
                unsigned bh[2][2], bl[2][2];
#pragma unroll
                for (int cc = 0; cc < 2; cc++) {
                    bh[cc][0] = q0h[cc][j]; bh[cc][1] = q1h[cc][j];
                    bl[cc][0] = q0l[cc][j]; bl[cc][1] = q1l[cc][j];
                }
#pragma unroll
                for (int cc = 0; cc < 2; cc++)
#pragma unroll
                    for (int mt = 0; mt < MT; mt++)
                        mma16816(acc3[pair * 2 + cc][mt], ah[mt], bh[cc]);
#pragma unroll
                for (int cc = 0; cc < 2; cc++)
#pragma unroll
                    for (int mt = 0; mt < MT; mt++)
                        mma16816(acc3[pair * 2 + cc][mt], ah[mt], bl[cc]);
#pragma unroll
                for (int cc = 0; cc < 2; cc++)
#pragma unroll
                    for (int mt = 0; mt < MT; mt++)
                        mma16816(acc3[pair * 2 + cc][mt], al[mt], bh[cc]);
            }
        }
    }

    // ---- final: softmax over 4 groups, gated combine, store fp32 ----
#pragma unroll
    for (int mt = 0; mt < MT; mt++)
#pragma unroll
        for (int rs = 0; rs < 2; rs++) {
            int row = (wm * MT + mt) * 16 + g + rs * 8;
            int h0 = wn * 8 + 2 * tg;
            float res[2];
#pragma unroll
            for (int e = 0; e < 2; e++) {
                int h = h0 + e;
                float v0 = acc3[0][mt][rs * 2 + e] + __ldg(b_z + h);
                float v1 = acc3[1][mt][rs * 2 + e] + __ldg(b_z + 64 + h);
                float v2 = acc3[2][mt][rs * 2 + e] + __ldg(b_z + 128 + h);
                float v3 = acc3[3][mt][rs * 2 + e] + __ldg(b_z + 192 + h);
                float mx = fmaxf(fmaxf(v0, v1), fmaxf(v2, v3));
                float e0 = __expf(v0 - mx), e1 = __expf(v1 - mx);
                float e2 = __expf(v2 - mx), e3 = __expf(v3 - mx);
                float inv = 1.f / (e0 + e1 + e2 + e3);
                float hh = rd_split(AHI, ALO, row, h, SAB);
                float hl = rd_split(AHI, ALO, row, 64 + h, SAB);
                float hr = rd_split(AHI, ALO, row, 128 + h, SAB);
                float uu = rd_split(AHI, ALO, row, 192 + h, SAB);
                res[e] = (e0 * hh + e1 * hl + e2 * hr + e3 * uu) * inv;
            }
            *(float2*)(up_out + (size_t)(r0 + row) * 64 + h0) = make_float2(res[0], res[1]);
        }
}

static const int SMEM_BYTES = ROWS * SAB * 2 + ROWS * SRB * 2 + ROWS * 8 * 4 + 64 * 8 * 4 + 256;

extern "C" void kernel_launch(void* const* d_in, const int* in_sizes, int n_in,
                              void* d_out, int out_size) {
    const float* contents = (const float*)d_in[0];
    const float* W_u = (const float*)d_in[1];
    const float* b_u = (const float*)d_in[2];
    const float* W_r = (const float*)d_in[3];
    const float* b_r = (const float*)d_in[4];
    const float* W_h = (const float*)d_in[5];
    const float* b_h = (const float*)d_in[6];
    const float* W_z = (const float*)d_in[7];
    const float* b_z = (const float*)d_in[8];
    float* out = (float*)d_out;

    float *upA = nullptr, *upB = nullptr;
    cudaGetSymbolAddress((void**)&upA, g_upA);
    cudaGetSymbolAddress((void**)&upB, g_upB);
    uint4 *prh, *prl, *phh, *phl, *pzh, *pzl;
    cudaGetSymbolAddress((void**)&prh, g_PrH); cudaGetSymbolAddress((void**)&prl, g_PrL);
    cudaGetSymbolAddress((void**)&phh, g_PhH); cudaGetSymbolAddress((void**)&phl, g_PhL);
    cudaGetSymbolAddress((void**)&pzh, g_PzH); cudaGetSymbolAddress((void**)&pzl, g_PzL);

    cudaFuncSetAttribute(grnn_level_kernel,
                         cudaFuncAttributeMaxDynamicSharedMemorySize, SMEM_BYTES);

    prep_pack<<<(4608 + 255) / 256, 256>>>(W_r, 192, 192, prh, prl);
    prep_pack<<<(1536 + 255) / 256, 256>>>(W_h, 64, 192, phh, phl);
    prep_pack<<<(8192 + 255) / 256, 256>>>(W_z, 256, 256, pzh, pzl);

    // Level 12 (top): up = u
    {
        int n = 64 << 12;
        size_t off = (size_t)64 * ((1 << 12) - 1) * 7;
        int total = n * 64;
        grnn_top_kernel<<<(total + 255) / 256, 256>>>(contents + off, W_u, b_u, upA, n);
    }

    // Levels 11..0
    const float* prev = upA;
    for (int j = 11; j >= 0; j--) {
        int n = 64 << j;
        size_t off = (size_t)64 * ((1 << j) - 1) * 7;
        float* outp = (j == 0) ? out : ((j & 1) ? upB : upA);
        grnn_level_kernel<<<n / ROWS, NT, SMEM_BYTES>>>(
            contents + off, prev, outp,
            W_u, b_u, prh, prl, b_r, phh, phl, b_h, pzh, pzl, b_z);
        prev = outp;
    }
}

// round 15
// speedup vs baseline: 1.2778x; 1.2778x over previous
#include <cuda_runtime.h>
#include <cuda_bf16.h>
#include <math.h>

// GRNNTransformGated via mma.sync.m16n8k16 bf16 (3-pass split ~ fp32 precision).
// K-outer GEMMs, pre-split weights in gmem, ldmatrix fragments, cp.async
// ping-pong B staging (stage tile i+2 strictly after compute(i)).
// NT=512 (16 warps, 2m x 8n, MT=2) big levels; NT=256 small levels.

#define SAB 528   // A buf row stride bytes; (528/4)%32=4 -> ldmatrix conflict-free
#define SRB 400   // rx buf row stride bytes
#define SBB 144   // B tile row stride bytes (64k bf16=128B + 16 pad)
#define BTILE 36864  // 256 rows * SBB

__device__ float g_upA[262144 * 64];
__device__ float g_upB[131072 * 64];

// pre-split weights (bf16 hi/lo), [n][K] row-major
__device__ unsigned short g_Wr_hi[36864], g_Wr_lo[36864];
__device__ unsigned short g_Wh_hi[12288], g_Wh_lo[12288];
__device__ unsigned short g_Wz_hi[65536], g_Wz_lo[65536];

__device__ __forceinline__ void split_pack(float a, float b, unsigned& hi, unsigned& lo) {
    __nv_bfloat16 ha = __float2bfloat16(a), hb = __float2bfloat16(b);
    __nv_bfloat16 la = __float2bfloat16(a - __bfloat162float(ha));
    __nv_bfloat16 lb = __float2bfloat16(b - __bfloat162float(hb));
    hi = (unsigned)__bfloat16_as_ushort(ha) | ((unsigned)__bfloat16_as_ushort(hb) << 16);
    lo = (unsigned)__bfloat16_as_ushort(la) | ((unsigned)__bfloat16_as_ushort(lb) << 16);
}
__device__ __forceinline__ float rd_split(const char* hi, const char* lo, int row, int col, int strideB) {
    return __bfloat162float(*(const __nv_bfloat16*)(hi + row * strideB + col * 2)) +
           __bfloat162float(*(const __nv_bfloat16*)(lo + row * strideB + col * 2));
}
__device__ __forceinline__ unsigned smem_u32(const void* p) {
    unsigned a;
    asm("{ .reg .u64 t; cvta.to.shared.u64 t, %1; cvt.u32.u64 %0, t; }" : "=r"(a) : "l"(p));
    return a;
}
__device__ __forceinline__ void mma16816(float* c, const unsigned* a, const unsigned* b) {
    asm volatile("mma.sync.aligned.m16n8k16.row.col.f32.bf16.bf16.f32 "
                 "{%0,%1,%2,%3}, {%4,%5,%6,%7}, {%8,%9}, {%0,%1,%2,%3};"
                 : "+f"(c[0]), "+f"(c[1]), "+f"(c[2]), "+f"(c[3])
                 : "r"(a[0]), "r"(a[1]), "r"(a[2]), "r"(a[3]), "r"(b[0]), "r"(b[1]));
}
#define LDSM_X4(d, addr) \
    asm volatile("ldmatrix.sync.aligned.m8n8.x4.shared.b16 {%0,%1,%2,%3}, [%4];" \
                 : "=r"((d)[0]), "=r"((d)[1]), "=r"((d)[2]), "=r"((d)[3]) : "r"(addr))
#define LDSM_X2(d, addr) \
    asm volatile("ldmatrix.sync.aligned.m8n8.x2.shared.b16 {%0,%1}, [%2];" \
                 : "=r"((d)[0]), "=r"((d)[1]) : "r"(addr))
#define CP_ASYNC16(dst, src) \
    asm volatile("cp.async.cg.shared.global [%0], [%1], 16;" :: "r"(dst), "l"(src))
#define CP_COMMIT() asm volatile("cp.async.commit_group;" ::: "memory")
__device__ __forceinline__ void cp_wait1() { asm volatile("cp.async.wait_group 1;" ::: "memory"); }
__device__ __forceinline__ void cp_wait0() { asm volatile("cp.async.wait_group 0;" ::: "memory"); }

// ---------------- weight prep: fp32 -> bf16 hi/lo (once per launch) ----------------
__global__ void prep_weights(const float* __restrict__ W_r,
                             const float* __restrict__ W_h,
                             const float* __restrict__ W_z) {
    int i = blockIdx.x * blockDim.x + threadIdx.x;
    float v; unsigned short* ph; unsigned short* pl; int k;
    if (i < 36864)       { v = W_r[i];            ph = g_Wr_hi; pl = g_Wr_lo; k = i; }
    else if (i < 49152)  { v = W_h[i - 36864];    ph = g_Wh_hi; pl = g_Wh_lo; k = i - 36864; }
    else if (i < 114688) { v = W_z[i - 49152];    ph = g_Wz_hi; pl = g_Wz_lo; k = i - 49152; }
    else return;
    __nv_bfloat16 h = __float2bfloat16(v);
    __nv_bfloat16 l = __float2bfloat16(v - __bfloat162float(h));
    ph[k] = __bfloat16_as_ushort(h);
    pl[k] = __bfloat16_as_ushort(l);
}

// ---------------- top level (j=12), 4 outputs / thread ----------------
__global__ void grnn_top_kernel(const float* __restrict__ contents,
                                const float* __restrict__ W_u,
                                const float* __restrict__ b_u,
                                float* __restrict__ up, int n) {
    int idx = blockIdx.x * blockDim.x + threadIdx.x;
    if (idx >= n * 16) return;
    int i = idx >> 4, hq = (idx & 15) * 4;
    float c[7];
#pragma unroll
    for (int f = 0; f < 7; f++) c[f] = __ldg(contents + (size_t)i * 7 + f);
    float4 r;
    float* rp = (float*)&r;
#pragma unroll
    for (int m = 0; m < 4; m++) {
        int h = hq + m;
        float acc = __ldg(b_u + h);
#pragma unroll
        for (int f = 0; f < 7; f++) acc = fmaf(c[f], __ldg(W_u + h * 7 + f), acc);
        rp[m] = fmaxf(acc, 0.f);
    }
    *(float4*)(up + (size_t)i * 64 + hq) = r;
}

// ---------------- fused level kernel ----------------
template <int NT>
__global__ __launch_bounds__(NT, 1) void grnn_level_kernel(
    const float* __restrict__ contents,
    const float* __restrict__ up_prev,
    float* __restrict__ up_out,
    const float* __restrict__ W_u, const float* __restrict__ b_u,
    const unsigned short* __restrict__ Wr_hi, const unsigned short* __restrict__ Wr_lo,
    const float* __restrict__ b_r,
    const unsigned short* __restrict__ Wh_hi, const unsigned short* __restrict__ Wh_lo,
    const float* __restrict__ b_h,
    const unsigned short* __restrict__ Wz_hi, const unsigned short* __restrict__ Wz_lo,
    const float* __restrict__ b_z)
{
    constexpr int ROWS = NT / 8;                 // 512 -> 64, 256 -> 32
    constexpr int MT = 2;
    constexpr int OF_ALO = ROWS * SAB;
    constexpr int OF_RHI = OF_ALO + ROWS * SAB;
    constexpr int OF_RLO = OF_RHI + ROWS * SRB;
    constexpr int OF_B0  = OF_RLO + ROWS * SRB;
    constexpr int OF_B1  = OF_B0 + BTILE;
    constexpr int OF_CS  = OF_B1 + BTILE;
    constexpr int OF_WU  = OF_CS + ROWS * 32;
    constexpr int OF_BUS = OF_WU + 2048;

    extern __shared__ char sm[];
    char* AHI = sm;            char* ALO = sm + OF_ALO;
    char* RHI = sm + OF_RHI;   char* RLO = sm + OF_RLO;
    float* cs  = (float*)(sm + OF_CS);
    float* wu  = (float*)(sm + OF_WU);
    float* bus = (float*)(sm + OF_BUS);

    const unsigned smb = smem_u32(sm);
    const unsigned uAHI = smb, uALO = smb + OF_ALO;
    const unsigned uRHI = smb + OF_RHI, uRLO = smb + OF_RLO;
    const unsigned uB0 = smb + OF_B0, uB1 = smb + OF_B1;

    const int t = threadIdx.x, lane = t & 31, w = t >> 5;
    const int wm = w >> 3, wn = w & 7, g = lane >> 2, tg = lane & 3;
    const int l16 = lane & 15;
    const unsigned aSel = ((lane >> 4) & 1) * 16;
    const unsigned bSel = ((lane >> 3) & 1) * 16;
    const int r0 = blockIdx.x * ROWS;

    // stage tile i (0..15) into buffer (i&1) via cp.async
    auto stage = [&](int i) {
        const unsigned short* W;
        int NR, Ksrc, k0; bool remap = false;
        if (i < 6)      { W = (i & 1) ? Wr_lo : Wr_hi; NR = 192; Ksrc = 192; k0 = (i >> 1) * 64; }
        else if (i < 8) { W = (i & 1) ? Wh_lo : Wh_hi; NR = 192; Ksrc = 192; k0 = 0; remap = true; }
        else            { W = (i & 1) ? Wz_lo : Wz_hi; NR = 256; Ksrc = 256; k0 = ((i - 8) >> 1) * 64; }
        unsigned dstB = (i & 1) ? uB1 : uB0;
        for (int e = t; e < NR * 8; e += NT) {
            int n = e >> 3, kq = (e & 7) * 8;
            int sr = remap ? (n & 63) : n;
            int sk = remap ? ((n >> 6) * 64 + kq) : (k0 + kq);
            CP_ASYNC16(dstB + n * SBB + kq * 2, W + (size_t)sr * Ksrc + sk);
        }
    };
    // call strictly AFTER compute of tile (inext-2) finished: frees buffer (inext&1)
    auto boundary = [&](int inext) {
        __syncthreads();                        // all reads of buffer (inext&1) done
        if (inext < 16) { stage(inext); CP_COMMIT(); cp_wait1(); }
        else cp_wait0();
        __syncthreads();                        // next tile visible
    };

    stage(0); CP_COMMIT();
    stage(1); CP_COMMIT();

    // ---- phase 0a ----
    for (int idx = t; idx < ROWS * 7; idx += NT) {
        int i = idx / 7, f = idx % 7;
        cs[i * 8 + f] = contents[(size_t)(r0 + i) * 7 + f];
    }
    for (int idx = t; idx < 64 * 7; idx += NT) wu[(idx / 7) * 8 + (idx % 7)] = W_u[idx];
    if (t < 64) bus[t] = b_u[t];
    for (int idx = t; idx < ROWS * 32; idx += NT) {
        int i = idx >> 5, q = idx & 31, side = q >> 4, qq = q & 15;
        float4 v = *(const float4*)(up_prev + ((size_t)2 * (r0 + i) + side) * 64 + qq * 4);
        unsigned h0, l0, h1, l1;
        split_pack(v.x, v.y, h0, l0); split_pack(v.z, v.w, h1, l1);
        int col = 64 + side * 64 + qq * 4;
        *(uint2*)(AHI + i * SAB + col * 2) = make_uint2(h0, h1);
        *(uint2*)(ALO + i * SAB + col * 2) = make_uint2(l0, l1);
    }
    __syncthreads();
    // ---- phase 0b: u = relu(c @ W_u^T + b_u) -> cols 192..255 ----
    for (int idx = t; idx < ROWS * 32; idx += NT) {
        int i = idx >> 5, cp = idx & 31;
        float a0 = bus[2 * cp], a1 = bus[2 * cp + 1];
#pragma unroll
        for (int f = 0; f < 7; f++) {
            float cv = cs[i * 8 + f];
            a0 = fmaf(cv, wu[(2 * cp) * 8 + f], a0);
            a1 = fmaf(cv, wu[(2 * cp + 1) * 8 + f], a1);
        }
        a0 = fmaxf(a0, 0.f); a1 = fmaxf(a1, 0.f);
        unsigned hi, lo; split_pack(a0, a1, hi, lo);
        *(unsigned*)(AHI + i * SAB + (192 + 2 * cp) * 2) = hi;
        *(unsigned*)(ALO + i * SAB + (192 + 2 * cp) * 2) = lo;
    }
    cp_wait1();                                 // tile 0 ready (tile 1 may be pending)
    __syncthreads();                            // hhu complete + tile 0 visible

    // ---- GEMM1 (tiles 0..5): rx = sigmoid(hhu @ W_r^T + b_r) * hhu ----
    float acc1[3][MT][4] = {};
    for (int kc = 0; kc < 3; kc++) {
        // hi tile (2kc) in uB0: ah*bh, al*bh
#pragma unroll
        for (int kk4 = 0; kk4 < 4; kk4++) {
            unsigned ah[MT][4], al[MT][4];
#pragma unroll
            for (int mt = 0; mt < MT; mt++) {
                unsigned off = (unsigned)(((wm * MT + mt) * 16 + l16) * SAB
                                          + (64 + kc * 64 + kk4 * 16) * 2) + aSel;
                LDSM_X4(ah[mt], uAHI + off);
                LDSM_X4(al[mt], uALO + off);
            }
            unsigned bh[3][2];
#pragma unroll
            for (int c = 0; c < 3; c++) {
                unsigned bo = (unsigned)((c * 64 + wn * 8 + (lane & 7)) * SBB + kk4 * 32) + bSel;
                LDSM_X2(bh[c], uB0 + bo);
            }
#pragma unroll
            for (int c = 0; c < 3; c++)
#pragma unroll
                for (int mt = 0; mt < MT; mt++) mma16816(acc1[c][mt], ah[mt], bh[c]);
#pragma unroll
            for (int c = 0; c < 3; c++)
#pragma unroll
                for (int mt = 0; mt < MT; mt++) mma16816(acc1[c][mt], al[mt], bh[c]);
        }
        boundary(2 * kc + 2);
        // lo tile (2kc+1) in uB1: ah*bl
#pragma unroll
        for (int kk4 = 0; kk4 < 4; kk4++) {
            unsigned ah[MT][4];
#pragma unroll
            for (int mt = 0; mt < MT; mt++) {
                unsigned off = (unsigned)(((wm * MT + mt) * 16 + l16) * SAB
                                          + (64 + kc * 64 + kk4 * 16) * 2) + aSel;
                LDSM_X4(ah[mt], uAHI + off);
            }
            unsigned bl[3][2];
#pragma unroll
            for (int c = 0; c < 3; c++) {
                unsigned bo = (unsigned)((c * 64 + wn * 8 + (lane & 7)) * SBB + kk4 * 32) + bSel;
                LDSM_X2(bl[c], uB1 + bo);
            }
#pragma unroll
            for (int c = 0; c < 3; c++)
#pragma unroll
                for (int mt = 0; mt < MT; mt++) mma16816(acc1[c][mt], ah[mt], bl[c]);
        }
        boundary(2 * kc + 3);
    }
    // epilogue 1: rx -> RHI/RLO; tiles 6,7 already staged & tile 6 complete
#pragma unroll
    for (int c = 0; c < 3; c++)
#pragma unroll
        for (int mt = 0; mt < MT; mt++)
#pragma unroll
            for (int rs = 0; rs < 2; rs++) {
                int row = (wm * MT + mt) * 16 + g + rs * 8;
                int o0 = c * 64 + wn * 8 + 2 * tg;
                float z0 = acc1[c][mt][rs * 2 + 0] + __ldg(b_r + o0);
                float z1 = acc1[c][mt][rs * 2 + 1] + __ldg(b_r + o0 + 1);
                float s0 = 1.f / (1.f + __expf(-z0));
                float s1 = 1.f / (1.f + __expf(-z1));
                float x0 = s0 * rd_split(AHI, ALO, row, 64 + o0, SAB);
                float x1 = s1 * rd_split(AHI, ALO, row, 64 + o0 + 1, SAB);
                unsigned hi, lo; split_pack(x0, x1, hi, lo);
                *(unsigned*)(RHI + row * SRB + o0 * 2) = hi;
                *(unsigned*)(RLO + row * SRB + o0 * 2) = lo;
            }
    __syncthreads();                            // rx visible (no staging here!)

    // ---- GEMM2 (tiles 6 hi / 7 lo): h_H = relu(rx @ W_h^T + b_h) ----
    float acc2[MT][4] = {};
#pragma unroll
    for (int kk = 0; kk < 12; kk++) {
        int kt = kk >> 2, k2 = kk & 3;
        unsigned ah[MT][4], al[MT][4];
#pragma unroll
        for (int mt = 0; mt < MT; mt++) {
            unsigned off = (unsigned)(((wm * MT + mt) * 16 + l16) * SRB + kk * 32) + aSel;
            LDSM_X4(ah[mt], uRHI + off);
            LDSM_X4(al[mt], uRLO + off);
        }
        unsigned bo = (unsigned)((kt * 64 + wn * 8 + (lane & 7)) * SBB + k2 * 32) + bSel;
        unsigned bh[2];
        LDSM_X2(bh, uB0 + bo);
#pragma unroll
        for (int mt = 0; mt < MT; mt++) mma16816(acc2[mt], ah[mt], bh);
#pragma unroll
        for (int mt = 0; mt < MT; mt++) mma16816(acc2[mt], al[mt], bh);
    }
    boundary(8);                                // tile 6 consumed -> stage tile 8
#pragma unroll
    for (int kk = 0; kk < 12; kk++) {
        int kt = kk >> 2, k2 = kk & 3;
        unsigned ah[MT][4];
#pragma unroll
        for (int mt = 0; mt < MT; mt++) {
            unsigned off = (unsigned)(((wm * MT + mt) * 16 + l16) * SRB + kk * 32) + aSel;
            LDSM_X4(ah[mt], uRHI + off);
        }
        unsigned bo = (unsigned)((kt * 64 + wn * 8 + (lane & 7)) * SBB + k2 * 32) + bSel;
        unsigned bl[2];
        LDSM_X2(bl, uB1 + bo);
#pragma unroll
        for (int mt = 0; mt < MT; mt++) mma16816(acc2[mt], ah[mt], bl);
    }
    boundary(9);                                // tile 7 consumed -> stage tile 9
    // epilogue 2: hH -> AHI/ALO cols 0..63
#pragma unroll
    for (int mt = 0; mt < MT; mt++)
#pragma unroll
        for (int rs = 0; rs < 2; rs++) {
            int row = (wm * MT + mt) * 16 + g + rs * 8;
            int h0 = wn * 8 + 2 * tg;
            float v0 = fmaxf(acc2[mt][rs * 2 + 0] + __ldg(b_h + h0), 0.f);
            float v1 = fmaxf(acc2[mt][rs * 2 + 1] + __ldg(b_h + h0 + 1), 0.f);
            unsigned hi, lo; split_pack(v0, v1, hi, lo);
            *(unsigned*)(AHI + row * SAB + h0 * 2) = hi;
            *(unsigned*)(ALO + row * SAB + h0 * 2) = lo;
        }
    __syncthreads();                            // hH visible (no staging here!)

    // ---- GEMM3 (tiles 8..15): z = [h_H | hhu] @ W_z^T + b_z ----
    float acc3[4][MT][4] = {};
    for (int kc = 0; kc < 4; kc++) {
#pragma unroll
        for (int kk4 = 0; kk4 < 4; kk4++) {
            unsigned ah[MT][4], al[MT][4];
#pragma unroll
            for (int mt = 0; mt < MT; mt++) {
                unsigned off = (unsigned)(((wm * MT + mt) * 16 + l16) * SAB
                                          + (kc * 64 + kk4 * 16) * 2) + aSel;
                LDSM_X4(ah[mt], uAHI + off);
                LDSM_X4(al[mt], uALO + off);
            }
            unsigned bh[4][2];
#pragma unroll
            for (int c = 0; c < 4; c++) {
                unsigned bo = (unsigned)((c * 64 + wn * 8 + (lane & 7)) * SBB + kk4 * 32) + bSel;
                LDSM_X2(bh[c], uB0 + bo);
            }
#pragma unroll
            for (int c = 0; c < 4; c++)
#pragma unroll
                for (int mt = 0; mt < MT; mt++) mma16816(acc3[c][mt], ah[mt], bh[c]);
#pragma unroll
            for (int c = 0; c < 4; c++)
#pragma unroll
                for (int mt = 0; mt < MT; mt++) mma16816(acc3[c][mt], al[mt], bh[c]);
        }
        boundary(2 * kc + 10);                  // hi tile (8+2kc) consumed
#pragma unroll
        for (int kk4 = 0; kk4 < 4; kk4++) {
            unsigned ah[MT][4];
#pragma unroll
            for (int mt = 0; mt < MT; mt++) {
                unsigned off = (unsigned)(((wm * MT + mt) * 16 + l16) * SAB
                                          + (kc * 64 + kk4 * 16) * 2) + aSel;
                LDSM_X4(ah[mt], uAHI + off);
            }
            unsigned bl[4][2];
#pragma unroll
            for (int c = 0; c < 4; c++) {
                unsigned bo = (unsigned)((c * 64 + wn * 8 + (lane & 7)) * SBB + kk4 * 32) + bSel;
                LDSM_X2(bl[c], uB1 + bo);
            }
#pragma unroll
            for (int c = 0; c < 4; c++)
#pragma unroll
                for (int mt = 0; mt < MT; mt++) mma16816(acc3[c][mt], ah[mt], bl[c]);
        }
        if (kc < 3) boundary(2 * kc + 11);      // lo tile (9+2kc) consumed
    }

    // ---- final: softmax over 4 groups, gated combine, store fp32 ----
#pragma unroll
    for (int mt = 0; mt < MT; mt++)
#pragma unroll
        for (int rs = 0; rs < 2; rs++) {
            int row = (wm * MT + mt) * 16 + g + rs * 8;
            int h0 = wn * 8 + 2 * tg;
            float res[2];
#pragma unroll
            for (int e = 0; e < 2; e++) {
                int h = h0 + e;
                float v0 = acc3[0][mt][rs * 2 + e] + __ldg(b_z + h);
                float v1 = acc3[1][mt][rs * 2 + e] + __ldg(b_z + 64 + h);
                float v2 = acc3[2][mt][rs * 2 + e] + __ldg(b_z + 128 + h);
                float v3 = acc3[3][mt][rs * 2 + e] + __ldg(b_z + 192 + h);
                float mx = fmaxf(fmaxf(v0, v1), fmaxf(v2, v3));
                float e0 = __expf(v0 - mx), e1 = __expf(v1 - mx);
                float e2 = __expf(v2 - mx), e3 = __expf(v3 - mx);
                float inv = 1.f / (e0 + e1 + e2 + e3);
                float hh = rd_split(AHI, ALO, row, h, SAB);
                float hl = rd_split(AHI, ALO, row, 64 + h, SAB);
                float hr = rd_split(AHI, ALO, row, 128 + h, SAB);
                float uu = rd_split(AHI, ALO, row, 192 + h, SAB);
                res[e] = (e0 * hh + e1 * hl + e2 * hr + e3 * uu) * inv;
            }
            *(float2*)(up_out + (size_t)(r0 + row) * 64 + h0) = make_float2(res[0], res[1]);
        }
}

static int smem_sz(int rows) {
    return rows * SAB * 2 + rows * SRB * 2 + 2 * BTILE + rows * 32 + 2048 + 256;
}

extern "C" void kernel_launch(void* const* d_in, const int* in_sizes, int n_in,
                              void* d_out, int out_size) {
    const float* contents = (const float*)d_in[0];
    const float* W_u = (const float*)d_in[1];
    const float* b_u = (const float*)d_in[2];
    const float* W_r = (const float*)d_in[3];
    const float* b_r = (const float*)d_in[4];
    const float* W_h = (const float*)d_in[5];
    const float* b_h = (const float*)d_in[6];
    const float* W_z = (const float*)d_in[7];
    const float* b_z = (const float*)d_in[8];
    float* out = (float*)d_out;

    float *upA = nullptr, *upB = nullptr;
    cudaGetSymbolAddress((void**)&upA, g_upA);
    cudaGetSymbolAddress((void**)&upB, g_upB);
    unsigned short *wrh, *wrl, *whh, *whl, *wzh, *wzl;
    cudaGetSymbolAddress((void**)&wrh, g_Wr_hi); cudaGetSymbolAddress((void**)&wrl, g_Wr_lo);
    cudaGetSymbolAddress((void**)&whh, g_Wh_hi); cudaGetSymbolAddress((void**)&whl, g_Wh_lo);
    cudaGetSymbolAddress((void**)&wzh, g_Wz_hi); cudaGetSymbolAddress((void**)&wzl, g_Wz_lo);

    const int smemBig = smem_sz(64), smemSmall = smem_sz(32);
    cudaFuncSetAttribute(grnn_level_kernel<512>,
                         cudaFuncAttributeMaxDynamicSharedMemorySize, smemBig);
    cudaFuncSetAttribute(grnn_level_kernel<256>,
                         cudaFuncAttributeMaxDynamicSharedMemorySize, smemSmall);

    prep_weights<<<(114688 + 255) / 256, 256>>>(W_r, W_h, W_z);

    // Level 12 (top): up = u
    {
        int n = 64 << 12;
        size_t off = (size_t)64 * ((1 << 12) - 1) * 7;
        grnn_top_kernel<<<(n * 16 + 255) / 256, 256>>>(contents + off, W_u, b_u, upA, n);
    }

    // Levels 11..0
    const float* prev = upA;
    for (int j = 11; j >= 0; j--) {
        int n = 64 << j;
        size_t off = (size_t)64 * ((1 << j) - 1) * 7;
        float* outp = (j == 0) ? out : ((j & 1) ? upB : upA);
        if (n >= 16384) {
            grnn_level_kernel<512><<<n / 64, 512, smemBig>>>(
                contents + off, prev, outp,
                W_u, b_u, wrh, wrl, b_r, whh, whl, b_h, wzh, wzl, b_z);
        } else {
            grnn_level_kernel<256><<<n / 32, 256, smemSmall>>>(
                contents + off, prev, outp,
                W_u, b_u, wrh, wrl, b_r, whh, whl, b_h, wzh, wzl, b_z);
        }
        prev = outp;
    }
}

// round 16
// speedup vs baseline: 1.4001x; 1.0957x over previous
#include <cuda_runtime.h>
#include <cuda_bf16.h>
#include <math.h>

// GRNNTransformGated via mma.sync.m16n8k16 bf16 (3-pass split ~ fp32 precision).
// K-outer GEMMs, pre-split weights, ldmatrix fragments, interleaved MMA issue
// (RAW distance 6-8), register-prefetched B staging. (R11 champion structure.)
// NT=512 (16 warps, 2m x 8n, MT=2) big levels; NT=256 (1m x 8n, MT=2) small.

#define SAB 528   // A buf row stride bytes; (528/4)%32=4 -> ldmatrix conflict-free
#define SRB 400   // rx buf row stride bytes; (400/4)%32=4
#define SBB 144   // B k-tile row stride bytes; (144/4)%32=4

__device__ float g_upA[262144 * 64];
__device__ float g_upB[131072 * 64];

// pre-split weights (bf16 hi/lo), [n][K] row-major
__device__ unsigned short g_Wr_hi[36864], g_Wr_lo[36864];
__device__ unsigned short g_Wh_hi[12288], g_Wh_lo[12288];
__device__ unsigned short g_Wz_hi[65536], g_Wz_lo[65536];

__device__ __forceinline__ void split_pack(float a, float b, unsigned& hi, unsigned& lo) {
    __nv_bfloat16 ha = __float2bfloat16(a), hb = __float2bfloat16(b);
    __nv_bfloat16 la = __float2bfloat16(a - __bfloat162float(ha));
    __nv_bfloat16 lb = __float2bfloat16(b - __bfloat162float(hb));
    hi = (unsigned)__bfloat16_as_ushort(ha) | ((unsigned)__bfloat16_as_ushort(hb) << 16);
    lo = (unsigned)__bfloat16_as_ushort(la) | ((unsigned)__bfloat16_as_ushort(lb) << 16);
}
__device__ __forceinline__ float rd_split(const char* hi, const char* lo, int row, int col, int strideB) {
    return __bfloat162float(*(const __nv_bfloat16*)(hi + row * strideB + col * 2)) +
           __bfloat162float(*(const __nv_bfloat16*)(lo + row * strideB + col * 2));
}
__device__ __forceinline__ unsigned smem_u32(const void* p) {
    unsigned a;
    asm("{ .reg .u64 t; cvta.to.shared.u64 t, %1; cvt.u32.u64 %0, t; }" : "=r"(a) : "l"(p));
    return a;
}
__device__ __forceinline__ void mma16816(float* c, const unsigned* a, const unsigned* b) {
    asm volatile("mma.sync.aligned.m16n8k16.row.col.f32.bf16.bf16.f32 "
                 "{%0,%1,%2,%3}, {%4,%5,%6,%7}, {%8,%9}, {%0,%1,%2,%3};"
                 : "+f"(c[0]), "+f"(c[1]), "+f"(c[2]), "+f"(c[3])
                 : "r"(a[0]), "r"(a[1]), "r"(a[2]), "r"(a[3]), "r"(b[0]), "r"(b[1]));
}
#define LDSM_X4(d, addr) \
    asm volatile("ldmatrix.sync.aligned.m8n8.x4.shared.b16 {%0,%1,%2,%3}, [%4];" \
                 : "=r"((d)[0]), "=r"((d)[1]), "=r"((d)[2]), "=r"((d)[3]) : "r"(addr))
#define LDSM_X2(d, addr) \
    asm volatile("ldmatrix.sync.aligned.m8n8.x2.shared.b16 {%0,%1}, [%2];" \
                 : "=r"((d)[0]), "=r"((d)[1]) : "r"(addr))

// ---------------- weight prep: fp32 -> bf16 hi/lo (once per launch) ----------------
__global__ void prep_weights(const float* __restrict__ W_r,
                             const float* __restrict__ W_h,
                             const float* __restrict__ W_z) {
    int i = blockIdx.x * blockDim.x + threadIdx.x;
    float v; unsigned short* ph; unsigned short* pl; int k;
    if (i < 36864)       { v = W_r[i];            ph = g_Wr_hi; pl = g_Wr_lo; k = i; }
    else if (i < 49152)  { v = W_h[i - 36864];    ph = g_Wh_hi; pl = g_Wh_lo; k = i - 36864; }
    else if (i < 114688) { v = W_z[i - 49152];    ph = g_Wz_hi; pl = g_Wz_lo; k = i - 49152; }
    else return;
    __nv_bfloat16 h = __float2bfloat16(v);
    __nv_bfloat16 l = __float2bfloat16(v - __bfloat162float(h));
    ph[k] = __bfloat16_as_ushort(h);
    pl[k] = __bfloat16_as_ushort(l);
}

// register prefetch of a B k-tile (NR virtual rows x 64 k, bf16 hi/lo)
template <int NT>
struct PF {
    static const int MAXE = 2048 / NT;
    uint4 h[MAXE], l[MAXE];
    __device__ __forceinline__ void load(const unsigned short* __restrict__ Whi,
                                         const unsigned short* __restrict__ Wlo,
                                         int NR, int Ksrc, int k0, int t, bool remap) {
#pragma unroll
        for (int i = 0; i < MAXE; i++) {
            int e = t + i * NT;
            if (e < NR * 8) {
                int n = e >> 3, kq = (e & 7) * 8;
                int sr = remap ? (n & 63) : n;
                int sk = remap ? ((n >> 6) * 64 + kq) : (k0 + kq);
                h[i] = *(const uint4*)(Whi + (size_t)sr * Ksrc + sk);
                l[i] = *(const uint4*)(Wlo + (size_t)sr * Ksrc + sk);
            }
        }
    }
    __device__ __forceinline__ void store(char* BHI, char* BLO, int NR, int t) {
#pragma unroll
        for (int i = 0; i < MAXE; i++) {
            int e = t + i * NT;
            if (e < NR * 8) {
                int n = e >> 3, kq = (e & 7) * 8;
                *(uint4*)(BHI + n * SBB + kq * 2) = h[i];
                *(uint4*)(BLO + n * SBB + kq * 2) = l[i];
            }
        }
    }
};

// ---------------- top level (j=12), 4 outputs / thread ----------------
__global__ void grnn_top_kernel(const float* __restrict__ contents,
                                const float* __restrict__ W_u,
                                const float* __restrict__ b_u,
                                float* __restrict__ up, int n) {
    int idx = blockIdx.x * blockDim.x + threadIdx.x;
    if (idx >= n * 16) return;
    int i = idx >> 4, hq = (idx & 15) * 4;
    float c[7];
#pragma unroll
    for (int f = 0; f < 7; f++) c[f] = __ldg(contents + (size_t)i * 7 + f);
    float4 r;
    float* rp = (float*)&r;
#pragma unroll
    for (int m = 0; m < 4; m++) {
        int h = hq + m;
        float acc = __ldg(b_u + h);
#pragma unroll
        for (int f = 0; f < 7; f++) acc = fmaf(c[f], __ldg(W_u + h * 7 + f), acc);
        rp[m] = fmaxf(acc, 0.f);
    }
    *(float4*)(up + (size_t)i * 64 + hq) = r;
}

// ---------------- fused level kernel: ROWS = NT/8 rows, MT=2 per warp ----------------
template <int NT>
__global__ __launch_bounds__(NT, 1) void grnn_level_kernel(
    const float* __restrict__ contents,
    const float* __restrict__ up_prev,
    float* __restrict__ up_out,
    const float* __restrict__ W_u, const float* __restrict__ b_u,
    const unsigned short* __restrict__ Wr_hi, const unsigned short* __restrict__ Wr_lo,
    const float* __restrict__ b_r,
    const unsigned short* __restrict__ Wh_hi, const unsigned short* __restrict__ Wh_lo,
    const float* __restrict__ b_h,
    const unsigned short* __restrict__ Wz_hi, const unsigned short* __restrict__ Wz_lo,
    const float* __restrict__ b_z)
{
    constexpr int ROWS = NT / 8;             // 512 -> 64, 256 -> 32
    constexpr int MT = 2;
    constexpr int OF_ALO = ROWS * SAB;
    constexpr int OF_RHI = OF_ALO + ROWS * SAB;
    constexpr int OF_RLO = OF_RHI + ROWS * SRB;
    constexpr int OF_BHI = OF_RLO + ROWS * SRB;
    constexpr int OF_BLO = OF_BHI + 256 * SBB;
    constexpr int OF_CS  = OF_BLO + 256 * SBB;
    constexpr int OF_WU  = OF_CS + ROWS * 8 * 4;
    constexpr int OF_BUS = OF_WU + 64 * 8 * 4;

    extern __shared__ char sm[];
    char* AHI = sm;            char* ALO = sm + OF_ALO;
    char* RHI = sm + OF_RHI;   char* RLO = sm + OF_RLO;
    char* BHI = sm + OF_BHI;   char* BLO = sm + OF_BLO;
    float* cs  = (float*)(sm + OF_CS);
    float* wu  = (float*)(sm + OF_WU);
    float* bus = (float*)(sm + OF_BUS);

    const unsigned smb = smem_u32(sm);
    const unsigned uAHI = smb, uALO = smb + OF_ALO;
    const unsigned uRHI = smb + OF_RHI, uRLO = smb + OF_RLO;
    const unsigned uBHI = smb + OF_BHI, uBLO = smb + OF_BLO;

    const int t = threadIdx.x, lane = t & 31, w = t >> 5;
    const int wm = w >> 3, wn = w & 7, g = lane >> 2, tg = lane & 3;
    const int l16 = lane & 15;
    const unsigned aSel = ((lane >> 4) & 1) * 16;
    const unsigned bSel = ((lane >> 3) & 1) * 16;
    const int r0 = blockIdx.x * ROWS;

    PF<NT> pf;
    pf.load(Wr_hi, Wr_lo, 192, 192, 0, t, false);   // W_r kc=0 in flight during phase 0

    // ---- phase 0a ----
    for (int idx = t; idx < ROWS * 7; idx += NT) {
        int i = idx / 7, f = idx % 7;
        cs[i * 8 + f] = contents[(size_t)(r0 + i) * 7 + f];
    }
    for (int idx = t; idx < 64 * 7; idx += NT) wu[(idx / 7) * 8 + (idx % 7)] = W_u[idx];
    if (t < 64) bus[t] = b_u[t];
    for (int idx = t; idx < ROWS * 32; idx += NT) {
        int i = idx >> 5, q = idx & 31, side = q >> 4, qq = q & 15;
        float4 v = *(const float4*)(up_prev + ((size_t)2 * (r0 + i) + side) * 64 + qq * 4);
        unsigned h0, l0, h1, l1;
        split_pack(v.x, v.y, h0, l0); split_pack(v.z, v.w, h1, l1);
        int col = 64 + side * 64 + qq * 4;
        *(uint2*)(AHI + i * SAB + col * 2) = make_uint2(h0, h1);
        *(uint2*)(ALO + i * SAB + col * 2) = make_uint2(l0, l1);
    }
    __syncthreads();
    // ---- phase 0b: u = relu(c @ W_u^T + b_u) -> cols 192..255 ----
    for (int idx = t; idx < ROWS * 32; idx += NT) {
        int i = idx >> 5, cp = idx & 31;
        float a0 = bus[2 * cp], a1 = bus[2 * cp + 1];
#pragma unroll
        for (int f = 0; f < 7; f++) {
            float cv = cs[i * 8 + f];
            a0 = fmaf(cv, wu[(2 * cp) * 8 + f], a0);
            a1 = fmaf(cv, wu[(2 * cp + 1) * 8 + f], a1);
        }
        a0 = fmaxf(a0, 0.f); a1 = fmaxf(a1, 0.f);
        unsigned hi, lo; split_pack(a0, a1, hi, lo);
        *(unsigned*)(AHI + i * SAB + (192 + 2 * cp) * 2) = hi;
        *(unsigned*)(ALO + i * SAB + (192 + 2 * cp) * 2) = lo;
    }

    // ---- GEMM1: rx = sigmoid(hhu @ W_r^T + b_r) * hhu; K-outer, 3 N-chunks ----
    float acc1[3][MT][4] = {};
    for (int kc = 0; kc < 3; kc++) {
        if (kc > 0) __syncthreads();            // prior B reads done
        pf.store(BHI, BLO, 192, t);
        if (kc < 2) pf.load(Wr_hi, Wr_lo, 192, 192, (kc + 1) * 64, t, false);
        else        pf.load(Wh_hi, Wh_lo, 192, 192, 0, t, true);   // stacked W_h next
        __syncthreads();
#pragma unroll
        for (int kk = 0; kk < 4; kk++) {
            unsigned ah[MT][4], al[MT][4];
#pragma unroll
            for (int mt = 0; mt < MT; mt++) {
                unsigned off = (unsigned)(((wm * MT + mt) * 16 + l16) * SAB
                                          + (64 + kc * 64 + kk * 16) * 2) + aSel;
                LDSM_X4(ah[mt], uAHI + off);
                LDSM_X4(al[mt], uALO + off);
            }
            unsigned bh[3][2], bl[3][2];
#pragma unroll
            for (int c = 0; c < 3; c++) {
                unsigned bo = (unsigned)((c * 64 + wn * 8 + (lane & 7)) * SBB + kk * 32) + bSel;
                LDSM_X2(bh[c], uBHI + bo);
                LDSM_X2(bl[c], uBLO + bo);
            }
            // interleaved passes: RAW distance 6
#pragma unroll
            for (int c = 0; c < 3; c++)
#pragma unroll
                for (int mt = 0; mt < MT; mt++) mma16816(acc1[c][mt], ah[mt], bh[c]);
#pragma unroll
            for (int c = 0; c < 3; c++)
#pragma unroll
                for (int mt = 0; mt < MT; mt++) mma16816(acc1[c][mt], ah[mt], bl[c]);
#pragma unroll
            for (int c = 0; c < 3; c++)
#pragma unroll
                for (int mt = 0; mt < MT; mt++) mma16816(acc1[c][mt], al[mt], bh[c]);
        }
    }
    // epilogue 1: rx -> RHI/RLO (unique rows per thread; no sync needed before)
#pragma unroll
    for (int c = 0; c < 3; c++)
#pragma unroll
        for (int mt = 0; mt < MT; mt++)
#pragma unroll
            for (int rs = 0; rs < 2; rs++) {
                int row = (wm * MT + mt) * 16 + g + rs * 8;
                int o0 = c * 64 + wn * 8 + 2 * tg;
                float z0 = acc1[c][mt][rs * 2 + 0] + __ldg(b_r + o0);
                float z1 = acc1[c][mt][rs * 2 + 1] + __ldg(b_r + o0 + 1);
                float s0 = 1.f / (1.f + __expf(-z0));
                float s1 = 1.f / (1.f + __expf(-z1));
                float x0 = s0 * rd_split(AHI, ALO, row, 64 + o0, SAB);
                float x1 = s1 * rd_split(AHI, ALO, row, 64 + o0 + 1, SAB);
                unsigned hi, lo; split_pack(x0, x1, hi, lo);
                *(unsigned*)(RHI + row * SRB + o0 * 2) = hi;
                *(unsigned*)(RLO + row * SRB + o0 * 2) = lo;
            }
    __syncthreads();                         // GEMM1 B reads done + rx visible
    pf.store(BHI, BLO, 192, t);              // stacked W_h
    pf.load(Wz_hi, Wz_lo, 256, 256, 0, t, false);
    __syncthreads();

    // ---- GEMM2: h_H = relu(rx @ W_h^T + b_h) -> AHI cols 0..63 ----
    {
        float acc[MT][4] = {};
#pragma unroll
        for (int kk = 0; kk < 12; kk++) {
            int kt = kk >> 2, k2 = kk & 3;
            unsigned ah[MT][4], al[MT][4];
#pragma unroll
            for (int mt = 0; mt < MT; mt++) {
                unsigned off = (unsigned)(((wm * MT + mt) * 16 + l16) * SRB + kk * 32) + aSel;
                LDSM_X4(ah[mt], uRHI + off);
                LDSM_X4(al[mt], uRLO + off);
            }
            unsigned bo = (unsigned)((kt * 64 + wn * 8 + (lane & 7)) * SBB + k2 * 32) + bSel;
            unsigned bh[2], bl[2];
            LDSM_X2(bh, uBHI + bo);
            LDSM_X2(bl, uBLO + bo);
#pragma unroll
            for (int mt = 0; mt < MT; mt++) mma16816(acc[mt], ah[mt], bh);
#pragma unroll
            for (int mt = 0; mt < MT; mt++) mma16816(acc[mt], ah[mt], bl);
#pragma unroll
            for (int mt = 0; mt < MT; mt++) mma16816(acc[mt], al[mt], bh);
        }
#pragma unroll
        for (int mt = 0; mt < MT; mt++)
#pragma unroll
            for (int rs = 0; rs < 2; rs++) {
                int row = (wm * MT + mt) * 16 + g + rs * 8;
                int h0 = wn * 8 + 2 * tg;
                float v0 = fmaxf(acc[mt][rs * 2 + 0] + __ldg(b_h + h0), 0.f);
                float v1 = fmaxf(acc[mt][rs * 2 + 1] + __ldg(b_h + h0 + 1), 0.f);
                unsigned hi, lo; split_pack(v0, v1, hi, lo);
                *(unsigned*)(AHI + row * SAB + h0 * 2) = hi;
                *(unsigned*)(ALO + row * SAB + h0 * 2) = lo;
            }
    }

    // ---- GEMM3: z = [h_H | hhu] @ W_z^T + b_z; K-outer, 4 N-chunks ----
    float acc3[4][MT][4] = {};
    for (int kc = 0; kc < 4; kc++) {
        __syncthreads();                    // prior B reads done; hH visible (kc=0)
        pf.store(BHI, BLO, 256, t);
        if (kc < 3) pf.load(Wz_hi, Wz_lo, 256, 256, (kc + 1) * 64, t, false);
        __syncthreads();
#pragma unroll
        for (int kk = 0; kk < 4; kk++) {
            unsigned ah[MT][4], al[MT][4];
#pragma unroll
            for (int mt = 0; mt < MT; mt++) {
                unsigned off = (unsigned)(((wm * MT + mt) * 16 + l16) * SAB
                                          + (kc * 64 + kk * 16) * 2) + aSel;
                LDSM_X4(ah[mt], uAHI + off);
                LDSM_X4(al[mt], uALO + off);
            }
            unsigned bh[4][2], bl[4][2];
#pragma unroll
            for (int c = 0; c < 4; c++) {
                unsigned bo = (unsigned)((c * 64 + wn * 8 + (lane & 7)) * SBB + kk * 32) + bSel;
                LDSM_X2(bh[c], uBHI + bo);
                LDSM_X2(bl[c], uBLO + bo);
            }
#pragma unroll
            for (int c = 0; c < 4; c++)
#pragma unroll
                for (int mt = 0; mt < MT; mt++) mma16816(acc3[c][mt], ah[mt], bh[c]);
#pragma unroll
            for (int c = 0; c < 4; c++)
#pragma unroll
                for (int mt = 0; mt < MT; mt++) mma16816(acc3[c][mt], ah[mt], bl[c]);
#pragma unroll
            for (int c = 0; c < 4; c++)
#pragma unroll
                for (int mt = 0; mt < MT; mt++) mma16816(acc3[c][mt], al[mt], bh[c]);
        }
    }

    // ---- final: softmax over 4 groups, gated combine, store fp32 ----
#pragma unroll
    for (int mt = 0; mt < MT; mt++)
#pragma unroll
        for (int rs = 0; rs < 2; rs++) {
            int row = (wm * MT + mt) * 16 + g + rs * 8;
            int h0 = wn * 8 + 2 * tg;
            float res[2];
#pragma unroll
            for (int e = 0; e < 2; e++) {
                int h = h0 + e;
                float v0 = acc3[0][mt][rs * 2 + e] + __ldg(b_z + h);
                float v1 = acc3[1][mt][rs * 2 + e] + __ldg(b_z + 64 + h);
                float v2 = acc3[2][mt][rs * 2 + e] + __ldg(b_z + 128 + h);
                float v3 = acc3[3][mt][rs * 2 + e] + __ldg(b_z + 192 + h);
                float mx = fmaxf(fmaxf(v0, v1), fmaxf(v2, v3));
                float e0 = __expf(v0 - mx), e1 = __expf(v1 - mx);
                float e2 = __expf(v2 - mx), e3 = __expf(v3 - mx);
                float inv = 1.f / (e0 + e1 + e2 + e3);
                float hh = rd_split(AHI, ALO, row, h, SAB);
                float hl = rd_split(AHI, ALO, row, 64 + h, SAB);
                float hr = rd_split(AHI, ALO, row, 128 + h, SAB);
                float uu = rd_split(AHI, ALO, row, 192 + h, SAB);
                res[e] = (e0 * hh + e1 * hl + e2 * hr + e3 * uu) * inv;
            }
            *(float2*)(up_out + (size_t)(r0 + row) * 64 + h0) = make_float2(res[0], res[1]);
        }
}

static int smem_sz(int rows) {
    return rows * SAB * 2 + rows * SRB * 2 + 256 * SBB * 2 + rows * 8 * 4 + 64 * 8 * 4 + 256;
}

extern "C" void kernel_launch(void* const* d_in, const int* in_sizes, int n_in,
                              void* d_out, int out_size) {
    const float* contents = (const float*)d_in[0];
    const float* W_u = (const float*)d_in[1];
    const float* b_u = (const float*)d_in[2];
    const float* W_r = (const float*)d_in[3];
    const float* b_r = (const float*)d_in[4];
    const float* W_h = (const float*)d_in[5];
    const float* b_h = (const float*)d_in[6];
    const float* W_z = (const float*)d_in[7];
    const float* b_z = (const float*)d_in[8];
    float* out = (float*)d_out;

    float *upA = nullptr, *upB = nullptr;
    cudaGetSymbolAddress((void**)&upA, g_upA);
    cudaGetSymbolAddress((void**)&upB, g_upB);
    unsigned short *wrh, *wrl, *whh, *whl, *wzh, *wzl;
    cudaGetSymbolAddress((void**)&wrh, g_Wr_hi); cudaGetSymbolAddress((void**)&wrl, g_Wr_lo);
    cudaGetSymbolAddress((void**)&whh, g_Wh_hi); cudaGetSymbolAddress((void**)&whl, g_Wh_lo);
    cudaGetSymbolAddress((void**)&wzh, g_Wz_hi); cudaGetSymbolAddress((void**)&wzl, g_Wz_lo);

    const int smemBig = smem_sz(64), smemSmall = smem_sz(32);
    cudaFuncSetAttribute(grnn_level_kernel<512>,
                         cudaFuncAttributeMaxDynamicSharedMemorySize, smemBig);
    cudaFuncSetAttribute(grnn_level_kernel<256>,
                         cudaFuncAttributeMaxDynamicSharedMemorySize, smemSmall);

    prep_weights<<<(114688 + 255) / 256, 256>>>(W_r, W_h, W_z);

    // Level 12 (top): up = u
    {
        int n = 64 << 12;
        size_t off = (size_t)64 * ((1 << 12) - 1) * 7;
        grnn_top_kernel<<<(n * 16 + 255) / 256, 256>>>(contents + off, W_u, b_u, upA, n);
    }

    // Levels 11..0
    const float* prev = upA;
    for (int j = 11; j >= 0; j--) {
        int n = 64 << j;
        size_t off = (size_t)64 * ((1 << j) - 1) * 7;
        float* outp = (j == 0) ? out : ((j & 1) ? upB : upA);
        if (n >= 16384) {
            grnn_level_kernel<512><<<n / 64, 512, smemBig>>>(
                contents + off, prev, outp,
                W_u, b_u, wrh, wrl, b_r, whh, whl, b_h, wzh, wzl, b_z);
        } else {
            grnn_level_kernel<256><<<n / 32, 256, smemSmall>>>(
                contents + off, prev, outp,
                W_u, b_u, wrh, wrl, b_r, whh, whl, b_h, wzh, wzl, b_z);
        }
        prev = outp;
    }
}